// round 12
// baseline (speedup 1.0000x reference)
#include <cuda_runtime.h>
#include <cuda_fp16.h>
#include <math.h>

#define BB 32
#define NN 512
#define TT 64
#define EE 128
#define OO 64
#define NITER 5
#define BNE (BB*NN*EE)      // 2^21
#define BN  (BB*NN)
#define L2E 1.442695040888963f

// ---------------- scratch ----------------
__device__ float    g_lit[2][BNE];
__device__ float    g_ah1[2][4][BN];
__device__ float    g_ah2[2][4][BN];
__device__ unsigned g_mask[4][BN*16];
__device__ float    g_xz[2][BB*TT*3*EE];
__device__ float    g_hfin[2][BB*EE];
__device__ float    g_rkT[2][3*EE*EE];
__device__ float    g_mid[2][BB*3*EE];
__device__ __half   g_embh[2][4ll*BNE];
__device__ __half   g_w1h[EE*EE];
__device__ __half   g_w2h[EE*EE];

// ================= helpers =================
__device__ __forceinline__ unsigned sptr(const void* p) {
    return (unsigned)__cvta_generic_to_shared(p);
}
__device__ __forceinline__ void cpasync16(unsigned s, const void* g) {
    asm volatile("cp.async.cg.shared.global [%0], [%1], 16;\n" :: "r"(s), "l"(g));
}
__device__ __forceinline__ void ldsm4(unsigned* r, unsigned addr) {
    asm volatile("ldmatrix.sync.aligned.m8n8.x4.shared.b16 {%0,%1,%2,%3},[%4];\n"
                 : "=r"(r[0]), "=r"(r[1]), "=r"(r[2]), "=r"(r[3]) : "r"(addr));
}
__device__ __forceinline__ void ldsm4t(unsigned* r, unsigned addr) {
    asm volatile("ldmatrix.sync.aligned.m8n8.x4.trans.shared.b16 {%0,%1,%2,%3},[%4];\n"
                 : "=r"(r[0]), "=r"(r[1]), "=r"(r[2]), "=r"(r[3]) : "r"(addr));
}
__device__ __forceinline__ void mma16816(float* d, const unsigned* a, unsigned b0, unsigned b1) {
    asm volatile(
        "mma.sync.aligned.m16n8k16.row.col.f32.f16.f16.f32 "
        "{%0,%1,%2,%3},{%4,%5,%6,%7},{%8,%9},{%0,%1,%2,%3};\n"
        : "+f"(d[0]), "+f"(d[1]), "+f"(d[2]), "+f"(d[3])
        : "r"(a[0]), "r"(a[1]), "r"(a[2]), "r"(a[3]), "r"(b0), "r"(b1));
}
__device__ __forceinline__ float ex2a(float x) {
    float y; asm("ex2.approx.f32 %0,%1;\n" : "=f"(y) : "f"(x)); return y;
}
__device__ __forceinline__ float tanha(float x) {
    float y; asm("tanh.approx.f32 %0,%1;\n" : "=f"(y) : "f"(x)); return y;
}

__device__ __forceinline__ void mma_ks(const __half* as_, int astr, int aoff,
                                       const __half* bs_, int ks,
                                       int wm, int wn, int lane, float acc[4][4][4])
{
    unsigned a[4][4], bfr[2][4];
#pragma unroll
    for (int mi = 0; mi < 4; mi++)
        ldsm4(a[mi], sptr(as_ + (wm + mi * 16 + (lane & 15)) * astr + aoff + (lane >> 4) * 8));
#pragma unroll
    for (int nb = 0; nb < 2; nb++)
        ldsm4t(bfr[nb], sptr(bs_ + (ks * 16 + (lane & 15)) * 136 + wn + nb * 16 + (lane >> 4) * 8));
#pragma unroll
    for (int mi = 0; mi < 4; mi++)
#pragma unroll
        for (int j = 0; j < 4; j++)
            mma16816(acc[mi][j], a[mi], bfr[j >> 1][(j & 1) * 2], bfr[j >> 1][(j & 1) * 2 + 1]);
}

// ================= fused per-iteration kernel =================
#define OFF_XL   9728
#define OFF_AS   (OFF_XL + 34816)     // 44544 (phase1 As; phases 2/3: whole-W buffer)
#define OFF_BS   (OFF_AS + 30720)     // 75264
#define SMEMSZ   (OFF_BS + 26112)     // 101376

__global__ void __launch_bounds__(256, 2) fused_k(
    const float* __restrict__ cw1, const float* __restrict__ cb1,
    const float* __restrict__ cw2, const float* __restrict__ cb2,
    const float* __restrict__ lw1, const float* __restrict__ lb1,
    const float* __restrict__ lw2, const float* __restrict__ lb2,
    int last, int rd, int wr)
{
    extern __shared__ __align__(16) char dyn[];
    float* s_ah1 = (float*)dyn;
    float* s_iZ  = s_ah1 + 128;
    float* s_ah2 = s_iZ + 128;
    float* s_red = s_ah2 + 512;
    float* s_sd1 = s_red + 256;
    float* s_sd2 = s_sd1 + 128;
    float* s_col = s_sd2 + 128;
    float* s_w1v = s_col + 128;
    float* s_w2v = s_w1v + 128;
    float* s_E   = s_w2v + 128;            // float2[128]
    __half2* s_Fh = (__half2*)(s_E + 256); // [512]
    __half* XL = (__half*)(dyn + OFF_XL);
    unsigned* s_mask = (unsigned*)XL;
    __half* Asp = (__half*)(dyn + OFF_AS);
    __half* Bsp = (__half*)(dyn + OFF_BS);
    __half* Ws  = (__half*)(dyn + OFF_AS);  // phases 2/3 full weight (128x136)

    const int z = blockIdx.z;
    const int c = z >> 5, b = z & 31;
    const int rowBase = blockIdx.x * 128;
    const int rowOff = b * NN + rowBase;
    const int tid = threadIdx.x, warp = tid >> 5, lane = tid & 31;
    const int wm = (warp >> 2) * 64, wn = (warp & 3) * 32;

    // ---------- prologue ----------
    const float* w1src = (c & 1) ? lw1 : cw1;
    const float* w2src = (c & 1) ? lw2 : cw2;
    const float bb1 = ((c & 1) ? lb1 : cb1)[0];
    const float bb2 = ((c & 1) ? lb2 : cb2)[0];
    if (tid < 128) {
        s_ah1[tid] = g_ah1[rd][c][rowOff + tid];
        s_w1v[tid] = w1src[tid];
        s_w2v[tid] = w2src[tid];
        ((float4*)s_ah2)[tid] = ((const float4*)(g_ah2[rd][c] + b * NN))[tid];
    }
    {
        const uint4* msrc = (const uint4*)(g_mask[c] + (long long)rowOff * 16);
        uint4* mdst = (uint4*)s_mask;
        mdst[tid] = msrc[tid];
        mdst[tid + 256] = msrc[tid + 256];
    }
    __syncthreads();

    // separable-exp precompute
#pragma unroll
    for (int i = tid; i < 512; i += 256) {
        float bq = fminf(s_ah2[i], 10.f);
        s_Fh[i] = __floats2half2_rn(ex2a(bq * L2E), ex2a(0.2f * bq * L2E));
    }
    if (tid < 128) {
        float a = s_ah1[tid];
        float K = a > 0.f ? a : 0.2f * a;
        ((float2*)s_E)[tid] = make_float2(ex2a((a - K) * L2E), ex2a((0.2f * a - K) * L2E));
    }
    __syncthreads();

    const int br = tid >> 4, bs4 = tid & 15;
    auto loadB2 = [&](const __half* src, int krow0, int stg) {
#pragma unroll
        for (int i = 0; i < 2; i++) {
            int r = br + i * 16;
            cpasync16(sptr(Bsp + stg * 4352 + r * 136 + bs4 * 8),
                      src + (long long)(krow0 + r) * 128 + bs4 * 8);
        }
        asm volatile("cp.async.commit_group;\n");
    };
    auto loadW = [&](const __half* src) {
#pragma unroll
        for (int i = 0; i < 8; i++) {
            int seg = i * 256 + tid;
            int r = seg >> 4, s16 = seg & 15;
            cpasync16(sptr(Ws + r * 136 + s16 * 8), src + r * 128 + s16 * 8);
        }
        asm volatile("cp.async.commit_group;\ncp.async.wait_group 0;\n" ::: "memory");
    };

    const int gr = tid >> 1, j0 = (tid & 1) * 16;
    const float negA = -s_ah1[gr];
    const float2 Ee = ((const float2*)s_E)[gr];
    float psum = 0.f;
    auto genP = [&](int ch, int stg) {
        unsigned mw = s_mask[gr * 16 + ch] >> j0;
        const float4* a2 = (const float4*)(s_ah2 + ch * 32 + j0);
        const uint4* f4 = (const uint4*)(s_Fh + ch * 32 + j0);
        __half2 hv[8];
#pragma unroll
        for (int q = 0; q < 4; q++) {
            float4 v = a2[q];
            uint4 fq = f4[q];
            const __half2* fh = (const __half2*)&fq;
            float vv[4] = {v.x, v.y, v.z, v.w};
            float p[4];
#pragma unroll
            for (int t = 0; t < 4; t++) {
                bool pos = vv[t] > negA;
                float2 ff = __half22float2(fh[t]);
                float pv = (pos ? Ee.x : Ee.y) * (pos ? ff.x : ff.y);
                p[t] = ((mw >> (q * 4 + t)) & 1u) ? pv : 0.f;
                psum += p[t];
            }
            hv[q * 2 + 0] = __floats2half2_rn(p[0], p[1]);
            hv[q * 2 + 1] = __floats2half2_rn(p[2], p[3]);
        }
        __half* as = Asp + stg * 5120;
        *(uint4*)(as + gr * 40 + j0) = *(uint4*)&hv[0];
        *(uint4*)(as + gr * 40 + j0 + 8) = *(uint4*)&hv[4];
    };

    float acc[4][4][4];
#pragma unroll
    for (int mi = 0; mi < 4; mi++)
#pragma unroll
        for (int j = 0; j < 4; j++)
#pragma unroll
            for (int q = 0; q < 4; q++) acc[mi][j][q] = 0.f;

    // ---------- phase 1: O = P @ emb ----------
    const __half* Bp = g_embh[rd] + (long long)z * (NN * EE);
    loadB2(Bp, 0, 0);
    loadB2(Bp, 32, 1);
    genP(0, 0);
    genP(1, 1);
    asm volatile("cp.async.wait_group 1;\n");
    __syncthreads();
#pragma unroll 4
    for (int ch = 0; ch < 16; ch++) {
        if (ch + 2 < 16) {
            loadB2(Bp, (ch + 2) * 32, (ch + 2) % 3);
            genP(ch + 2, (ch + 2) % 3);
        }
        const __half* as = Asp + (ch % 3) * 5120;
        const __half* bs_ = Bsp + (ch % 3) * 4352;
#pragma unroll
        for (int ks = 0; ks < 2; ks++)
            mma_ks(as, 40, ks * 16, bs_, ks, wm, wn, lane, acc);
        if (ch + 2 < 16) asm volatile("cp.async.wait_group 1;\n");
        else             asm volatile("cp.async.wait_group 0;\n");
        __syncthreads();
    }

    s_red[tid] = psum;
    __syncthreads();
    if (tid < 128) {
        float s2 = s_red[2 * tid] + s_red[2 * tid + 1];
        s_iZ[tid] = (s2 > 0.f) ? __fdividef(1.f, s2) : 0.f;
    }
    __syncthreads();

#pragma unroll
    for (int mi = 0; mi < 4; mi++)
#pragma unroll
        for (int h = 0; h < 2; h++) {
            const int r = wm + mi * 16 + (lane >> 2) + h * 8;
            const float rs = s_iZ[r];
#pragma unroll
            for (int j = 0; j < 4; j++) {
                const int c0 = wn + j * 8 + (lane & 3) * 2;
                *(__half2*)(XL + r * 136 + c0) =
                    __floats2half2_rn(acc[mi][j][h * 2] * rs, acc[mi][j][h * 2 + 1] * rs);
            }
        }
    __syncthreads();

    // ---------- phase 2: H = relu(O @ W1), whole W1 staged ----------
#pragma unroll
    for (int mi = 0; mi < 4; mi++)
#pragma unroll
        for (int j = 0; j < 4; j++)
#pragma unroll
            for (int q = 0; q < 4; q++) acc[mi][j][q] = 0.f;
    loadW(g_w1h);
    __syncthreads();
#pragma unroll
    for (int st = 0; st < 8; st++)
        mma_ks(XL, 136, st * 16, Ws, st, wm, wn, lane, acc);
    __syncthreads();
#pragma unroll
    for (int mi = 0; mi < 4; mi++)
#pragma unroll
        for (int h = 0; h < 2; h++) {
            const int r = wm + mi * 16 + (lane >> 2) + h * 8;
#pragma unroll
            for (int j = 0; j < 4; j++) {
                const int c0 = wn + j * 8 + (lane & 3) * 2;
                *(__half2*)(XL + r * 136 + c0) =
                    __floats2half2_rn(fmaxf(acc[mi][j][h * 2], 0.f),
                                      fmaxf(acc[mi][j][h * 2 + 1], 0.f));
            }
        }
    if (tid < 128) { s_sd1[tid] = 0.f; s_sd2[tid] = 0.f; s_col[tid] = 0.f; }

    // ---------- phase 3: E = tanh(lit + H @ W2), whole W2 staged ----------
#pragma unroll
    for (int mi = 0; mi < 4; mi++)
#pragma unroll
        for (int j = 0; j < 4; j++)
#pragma unroll
            for (int q = 0; q < 4; q++) acc[mi][j][q] = 0.f;
    loadW(g_w2h);
    __syncthreads();   // W2 ready + XL(H) writes + s_sd zeroing visible
#pragma unroll
    for (int st = 0; st < 8; st++)
        mma_ks(XL, 136, st * 16, Ws, st, wm, wn, lane, acc);

    // epilogue
    const float* litp = g_lit[c >> 1] + ((long long)(b * NN + rowBase)) * EE;
    __half* embp = g_embh[wr] + (long long)z * (NN * EE) + (long long)rowBase * EE;
    float colacc[8];
#pragma unroll
    for (int q = 0; q < 8; q++) colacc[q] = 0.f;
#pragma unroll
    for (int mi = 0; mi < 4; mi++)
#pragma unroll
        for (int h = 0; h < 2; h++) {
            const int r = wm + mi * 16 + (lane >> 2) + h * 8;
            float d1 = 0.f, d2 = 0.f;
#pragma unroll
            for (int j = 0; j < 4; j++) {
                const int c0 = wn + j * 8 + (lane & 3) * 2;
                float2 l = *(const float2*)(litp + (long long)r * EE + c0);
                float x0 = tanha(l.x + acc[mi][j][h * 2]);
                float x1 = tanha(l.y + acc[mi][j][h * 2 + 1]);
                *(__half2*)(embp + (long long)r * EE + c0) = __floats2half2_rn(x0, x1);
                d1 = fmaf(x0, s_w1v[c0], fmaf(x1, s_w1v[c0 + 1], d1));
                d2 = fmaf(x0, s_w2v[c0], fmaf(x1, s_w2v[c0 + 1], d2));
                colacc[j * 2 + 0] += x0;
                colacc[j * 2 + 1] += x1;
            }
            atomicAdd(&s_sd1[r], d1);
            atomicAdd(&s_sd2[r], d2);
        }
    if (last) {
#pragma unroll
        for (int j = 0; j < 4; j++) {
            const int c0 = wn + j * 8 + (lane & 3) * 2;
            atomicAdd(&s_col[c0], colacc[j * 2]);
            atomicAdd(&s_col[c0 + 1], colacc[j * 2 + 1]);
        }
    }
    __syncthreads();
    if (tid < 128) {
        g_ah1[wr][c][rowOff + tid] = s_sd1[tid] + bb1;
        g_ah2[wr][c][rowOff + tid] = s_sd2[tid] + bb2;
        if (last)
            atomicAdd(&g_mid[c >> 1][b * 3 * EE + (c & 1) * EE + tid], s_col[tid]);
    }
}

// ---------------- literal GEMM + fused init epilogue ----------------
// writes g_lit, g_embh[0] (both graph slots), and initial g_ah1/g_ah2[0]
__global__ void __launch_bounds__(256) litgemm_k(
    const float* __restrict__ L1, const float* __restrict__ W1,
    const float* __restrict__ L2, const float* __restrict__ W2,
    const float* __restrict__ cw1, const float* __restrict__ cb1,
    const float* __restrict__ cw2, const float* __restrict__ cb2,
    const float* __restrict__ lw1, const float* __restrict__ lb1,
    const float* __restrict__ lw2, const float* __restrict__ lb2)
{
    constexpr int BM = 128, BK = 8, TM = 8, TN = 8;
    __shared__ float As[BK][BM];
    __shared__ float Bsf[BK][128];
    __shared__ float s_w[4][128];
    const int s = blockIdx.z;
    const float* A = s ? L2 : L1;
    const float* Bm = s ? W2 : W1;
    float* C = g_lit[s];
    const int rowBase = blockIdx.x * BM;
    const int tid = threadIdx.x;
    const int tx = tid & 15, ty = tid >> 4;
    const int aRow = tid >> 1, aCol = (tid & 1) * 4;
    const int bRow = tid >> 5, bCol = (tid & 31) * 4;
    // attention weights to smem
    for (int i = tid; i < 512; i += 256) {
        int type = i >> 7, k = i & 127;
        const float* src = (type == 0) ? cw1 : (type == 1) ? cw2 : (type == 2) ? lw1 : lw2;
        s_w[type][k] = src[k];
    }
    float acc[TM][TN];
#pragma unroll
    for (int i = 0; i < TM; i++)
#pragma unroll
        for (int j = 0; j < TN; j++) acc[i][j] = 0.f;
    const float* Aptr = A + (long long)(rowBase + aRow) * EE + aCol;
    const float* Bptr = Bm + (long long)bRow * EE + bCol;
    for (int k0 = 0; k0 < EE; k0 += BK) {
        float4 av = *(const float4*)(Aptr + k0);
        float4 bv = *(const float4*)(Bptr + (long long)k0 * EE);
        As[aCol + 0][aRow] = av.x; As[aCol + 1][aRow] = av.y;
        As[aCol + 2][aRow] = av.z; As[aCol + 3][aRow] = av.w;
        *(float4*)&Bsf[bRow][bCol] = bv;
        __syncthreads();
#pragma unroll
        for (int k = 0; k < BK; k++) {
            float ra[TM], rb[TN];
            *(float4*)&ra[0] = *(const float4*)&As[k][ty * TM];
            *(float4*)&ra[4] = *(const float4*)&As[k][ty * TM + 4];
            *(float4*)&rb[0] = *(const float4*)&Bsf[k][tx * TN];
            *(float4*)&rb[4] = *(const float4*)&Bsf[k][tx * TN + 4];
#pragma unroll
            for (int i = 0; i < TM; i++)
#pragma unroll
                for (int j = 0; j < TN; j++)
                    acc[i][j] = fmaf(ra[i], rb[j], acc[i][j]);
        }
        __syncthreads();
    }
    const float bc1 = cb1[0], bc2 = cb2[0], bl1 = lb1[0], bl2 = lb2[0];
#pragma unroll
    for (int i = 0; i < TM; i++) {
        const int row = rowBase + ty * TM + i;
        const int bb = row >> 9, n = row & 511;
        float* crow = C + (long long)row * EE + tx * TN;
        __half* e0 = g_embh[0] + ((long long)(s * 64 + bb) * NN + n) * EE + tx * TN;
        __half* e1 = g_embh[0] + ((long long)(s * 64 + 32 + bb) * NN + n) * EE + tx * TN;
        float dc1 = 0.f, dc2 = 0.f, dl1 = 0.f, dl2 = 0.f;
#pragma unroll
        for (int j0 = 0; j0 < TN; j0 += 4) {
            float4 v;
            v.x = acc[i][j0 + 0]; v.y = acc[i][j0 + 1];
            v.z = acc[i][j0 + 2]; v.w = acc[i][j0 + 3];
            *(float4*)(crow + j0) = v;
            float rv[4] = {fmaxf(v.x, 0.f), fmaxf(v.y, 0.f), fmaxf(v.z, 0.f), fmaxf(v.w, 0.f)};
            __half2 h01 = __floats2half2_rn(rv[0], rv[1]);
            __half2 h23 = __floats2half2_rn(rv[2], rv[3]);
            *(__half2*)(e0 + j0) = h01; *(__half2*)(e0 + j0 + 2) = h23;
            *(__half2*)(e1 + j0) = h01; *(__half2*)(e1 + j0 + 2) = h23;
#pragma unroll
            for (int q = 0; q < 4; q++) {
                const int col = tx * TN + j0 + q;
                dc1 = fmaf(rv[q], s_w[0][col], dc1);
                dc2 = fmaf(rv[q], s_w[1][col], dc2);
                dl1 = fmaf(rv[q], s_w[2][col], dl1);
                dl2 = fmaf(rv[q], s_w[3][col], dl2);
            }
        }
#pragma unroll
        for (int o = 8; o; o >>= 1) {
            dc1 += __shfl_xor_sync(0xffffffffu, dc1, o);
            dc2 += __shfl_xor_sync(0xffffffffu, dc2, o);
            dl1 += __shfl_xor_sync(0xffffffffu, dl1, o);
            dl2 += __shfl_xor_sync(0xffffffffu, dl2, o);
        }
        if (tx == 0) {
            g_ah1[0][2 * s][row] = dc1 + bc1;
            g_ah2[0][2 * s][row] = dc2 + bc2;
            g_ah1[0][2 * s + 1][row] = dl1 + bl1;
            g_ah2[0][2 * s + 1][row] = dl2 + bl2;
        }
    }
}

// ---------------- xz GEMM, z-batched over both sides ----------------
__global__ void __launch_bounds__(256) sgemm_xz(
    const float* __restrict__ A1, const float* __restrict__ B1, const float* __restrict__ e1,
    const float* __restrict__ A2, const float* __restrict__ B2, const float* __restrict__ e2)
{
    constexpr int BM = 128, BNt = 128, BK = 8, TM = 8, TN = 8;
    constexpr int Nn = 3 * EE, K = EE;
    __shared__ float As[BK][BM];
    __shared__ float Bsf[BK][BNt];
    const int side = blockIdx.z;
    const float* A = side ? A2 : A1;
    const float* Bm = side ? B2 : B1;
    const float* extra = side ? e2 : e1;
    float* C = g_xz[side];
    const int rowBase = blockIdx.x * BM;
    const int colBase = blockIdx.y * BNt;
    const int tid = threadIdx.x;
    const int tx = tid & 15, ty = tid >> 4;
    const int aRow = tid >> 1, aCol = (tid & 1) * 4;
    const int bRow = tid >> 5, bCol = (tid & 31) * 4;
    float acc[TM][TN];
#pragma unroll
    for (int i = 0; i < TM; i++)
#pragma unroll
        for (int j = 0; j < TN; j++) acc[i][j] = 0.f;
    const float* Aptr = A + (long long)(rowBase + aRow) * K + aCol;
    const float* Bptr = Bm + (long long)bRow * Nn + colBase + bCol;
    for (int k0 = 0; k0 < K; k0 += BK) {
        float4 av = *(const float4*)(Aptr + k0);
        float4 bv = *(const float4*)(Bptr + (long long)k0 * Nn);
        As[aCol + 0][aRow] = av.x; As[aCol + 1][aRow] = av.y;
        As[aCol + 2][aRow] = av.z; As[aCol + 3][aRow] = av.w;
        *(float4*)&Bsf[bRow][bCol] = bv;
        __syncthreads();
#pragma unroll
        for (int k = 0; k < BK; k++) {
            float ra[TM], rb[TN];
            *(float4*)&ra[0] = *(const float4*)&As[k][ty * TM];
            *(float4*)&ra[4] = *(const float4*)&As[k][ty * TM + 4];
            *(float4*)&rb[0] = *(const float4*)&Bsf[k][tx * TN];
            *(float4*)&rb[4] = *(const float4*)&Bsf[k][tx * TN + 4];
#pragma unroll
            for (int i = 0; i < TM; i++)
#pragma unroll
                for (int j = 0; j < TN; j++)
                    acc[i][j] = fmaf(ra[i], rb[j], acc[i][j]);
        }
        __syncthreads();
    }
#pragma unroll
    for (int i = 0; i < TM; i++) {
        int row = rowBase + ty * TM + i;
        float* crow = C + (long long)row * Nn + colBase + tx * TN;
#pragma unroll
        for (int j0 = 0; j0 < TN; j0 += 4) {
            float4 v;
            v.x = acc[i][j0 + 0] + extra[colBase + tx * TN + j0 + 0];
            v.y = acc[i][j0 + 1] + extra[colBase + tx * TN + j0 + 1];
            v.z = acc[i][j0 + 2] + extra[colBase + tx * TN + j0 + 2];
            v.w = acc[i][j0 + 3] + extra[colBase + tx * TN + j0 + 3];
            *(float4*)(crow + j0) = v;
        }
    }
}

// ---------------- G -> bitmask + transpose rk + zero g_mid + fp16 weights ----------------
__global__ void __launch_bounds__(256) mask_k(
    const int* __restrict__ g0, const int* __restrict__ g1,
    const int* __restrict__ g2, const int* __restrict__ g3,
    const float* __restrict__ rk1, const float* __restrict__ rk2,
    const float* __restrict__ m1, const float* __restrict__ m2)
{
    const long long flat = (long long)blockIdx.x * 256 + threadIdx.x;
    if (flat < 2 * BB * 3 * EE) ((float*)g_mid)[flat] = 0.f;
    if (flat < 2 * 3 * EE * EE) {
        const int s = (int)(flat / (3 * EE * EE));
        const int r = (int)(flat % (3 * EE * EE));
        const int j = r / EE, k = r % EE;
        const float* rk = s ? rk2 : rk1;
        g_rkT[s][r] = rk[k * 3 * EE + j];
    }
    if (flat < EE * EE) g_w1h[flat] = __float2half_rn(m1[flat]);
    else if (flat < 2 * EE * EE) g_w2h[flat - EE * EE] = __float2half_rn(m2[flat - EE * EE]);
    const long long gid = flat >> 5;
    const int lane = threadIdx.x & 31;
    const int c = (int)(gid >> 18);
    const long long r = gid & 262143;
    const long long rowrem = r >> 4;
    const int w = (int)(r & 15);
    const int* G = (c == 0) ? g0 : (c == 1) ? g1 : (c == 2) ? g2 : g3;
    int val = G[rowrem * NN + w * 32 + lane];
    unsigned m = __ballot_sync(0xffffffffu, val != 0);
    if (lane == 0) g_mask[c][rowrem * 16 + w] = m;
}

// ---------------- GRU (reset_after): split-K, 768 threads ----------------
__global__ void __launch_bounds__(768, 1) gru_k(const float* __restrict__ b1,
                                                const float* __restrict__ b2)
{
    const int s = blockIdx.x >> 5, b = blockIdx.x & 31;
    const float* xz = g_xz[s] + (long long)b * TT * 3 * EE;
    const float* brp = (s ? b2 : b1) + 3 * EE;
    const int t = threadIdx.x;          // 0..767
    const int o = t >> 1, hf = t & 1;   // output 0..383, half 0/1

    // this thread's 64-float weight half-row
    float4 w[16];
    {
        const float4* wsrc = (const float4*)(g_rkT[s] + (long long)o * EE + hf * 64);
#pragma unroll
        for (int i = 0; i < 16; i++) w[i] = wsrc[i];
    }

    __shared__ __align__(16) float hs[EE];
    __shared__ float xs[3 * EE];
    __shared__ float part[768];
    float brz = 0.f, brr = 0.f, brh = 0.f;
    if (t < 128) {
        hs[t] = 0.f;
        brz = brp[t]; brr = brp[EE + t]; brh = brp[2 * EE + t];
    }
    __syncthreads();

    for (int st = 0; st < TT; st++) {
        float xv = 0.f;
        if (t < 384) xv = xz[st * 3 * EE + t];
        const float4* h4 = ((const float4*)hs) + hf * 16;
        float a0 = 0.f, a1 = 0.f, a2 = 0.f, a3 = 0.f;
#pragma unroll
        for (int qq = 0; qq < 16; qq += 4) {
            float4 wv, hv;
            wv = w[qq + 0]; hv = h4[qq + 0];
            a0 = fmaf(wv.x, hv.x, a0); a0 = fmaf(wv.y, hv.y, a0);
            a0 = fmaf(wv.z, hv.z, a0); a0 = fmaf(wv.w, hv.w, a0);
            wv = w[qq + 1]; hv = h4[qq + 1];
            a1 = fmaf(wv.x, hv.x, a1); a1 = fmaf(wv.y, hv.y, a1);
            a1 = fmaf(wv.z, hv.z, a1); a1 = fmaf(wv.w, hv.w, a1);
            wv = w[qq + 2]; hv = h4[qq + 2];
            a2 = fmaf(wv.x, hv.x, a2); a2 = fmaf(wv.y, hv.y, a2);
            a2 = fmaf(wv.z, hv.z, a2); a2 = fmaf(wv.w, hv.w, a2);
            wv = w[qq + 3]; hv = h4[qq + 3];
            a3 = fmaf(wv.x, hv.x, a3); a3 = fmaf(wv.y, hv.y, a3);
            a3 = fmaf(wv.z, hv.z, a3); a3 = fmaf(wv.w, hv.w, a3);
        }
        part[t] = (a0 + a1) + (a2 + a3);
        if (t < 384) xs[t] = xv;
        __syncthreads();
        if (t < 128) {
            float hzz = part[2 * t] + part[2 * t + 1] + brz;
            float hzr = part[2 * (128 + t)] + part[2 * (128 + t) + 1] + brr;
            float hzh = part[2 * (256 + t)] + part[2 * (256 + t) + 1] + brh;
            float zz = __fdividef(1.f, 1.f + __expf(-(xs[t] + hzz)));
            float rr = __fdividef(1.f, 1.f + __expf(-(xs[EE + t] + hzr)));
            float hh = tanha(xs[2 * EE + t] + rr * hzh);
            hs[t] = zz * hs[t] + (1.f - zz) * hh;
        }
        __syncthreads();
    }
    if (t < 128) g_hfin[s][b * EE + t] = hs[t];
}

// ---------------- merged head ----------------
__global__ void __launch_bounds__(128) outfinal_k(const float* __restrict__ Wout,
                                                  const float* __restrict__ bout,
                                                  float* __restrict__ out)
{
    const int b = blockIdx.x, tid = threadIdx.x;
    __shared__ float ms[2][3 * EE];
    __shared__ float sh[128];
    __shared__ float red[6];
    for (int i = tid; i < 2 * 3 * EE; i += 128) {
        int s = i / (3 * EE), k = i % (3 * EE);
        ms[s][k] = (k < 2 * EE) ? g_mid[s][b * 3 * EE + k] : g_hfin[s][b * EE + (k - 2 * EE)];
    }
    __syncthreads();
    const int s = tid >> 6, o = tid & 63;
    float acc = bout[o];
    for (int k = 0; k < 3 * EE; k++) acc = fmaf(ms[s][k], Wout[k * OO + o], acc);
    sh[tid] = acc;
    __syncthreads();
    if (tid < 64) {
        float x = sh[tid], y = sh[tid + 64];
        float d = x * y, nx = x * x, ny = y * y;
#pragma unroll
        for (int off = 16; off; off >>= 1) {
            d  += __shfl_xor_sync(0xffffffffu, d, off);
            nx += __shfl_xor_sync(0xffffffffu, nx, off);
            ny += __shfl_xor_sync(0xffffffffu, ny, off);
        }
        if ((tid & 31) == 0) {
            red[(tid >> 5) * 3 + 0] = d;
            red[(tid >> 5) * 3 + 1] = nx;
            red[(tid >> 5) * 3 + 2] = ny;
        }
    }
    __syncthreads();
    if (tid == 0) {
        float D = red[0] + red[3], X = red[1] + red[4], Y = red[2] + red[5];
        float cosv = D * rsqrtf(fmaxf(X, 1e-12f)) * rsqrtf(fmaxf(Y, 1e-12f));
        out[b] = (cosv + 1.f) * 0.5f;
    }
}

// ---------------- launch ----------------
extern "C" void kernel_launch(void* const* d_in, const int* in_sizes, int n_in,
                              void* d_out, int out_size)
{
    const int*   CFG1 = (const int*)d_in[0];
    const int*   LFG1 = (const int*)d_in[1];
    const float* LIT1 = (const float*)d_in[2];
    const float* SEM1 = (const float*)d_in[3];
    const int*   CFG2 = (const int*)d_in[4];
    const int*   LFG2 = (const int*)d_in[5];
    const float* LIT2 = (const float*)d_in[6];
    const float* SEM2 = (const float*)d_in[7];
    const float* Wl1  = (const float*)d_in[8];
    const float* g1k  = (const float*)d_in[9];
    const float* g1rk = (const float*)d_in[10];
    const float* g1b  = (const float*)d_in[11];
    const float* Wl2  = (const float*)d_in[12];
    const float* g2k  = (const float*)d_in[13];
    const float* g2rk = (const float*)d_in[14];
    const float* g2b  = (const float*)d_in[15];
    const float* cw1  = (const float*)d_in[16];
    const float* cb1  = (const float*)d_in[17];
    const float* cw2  = (const float*)d_in[18];
    const float* cb2  = (const float*)d_in[19];
    const float* lw1  = (const float*)d_in[20];
    const float* lb1  = (const float*)d_in[21];
    const float* lw2  = (const float*)d_in[22];
    const float* lb2  = (const float*)d_in[23];
    const float* mlp1 = (const float*)d_in[24];
    const float* mlp2 = (const float*)d_in[25];
    const float* Wout = (const float*)d_in[26];
    const float* bout = (const float*)d_in[27];

    cudaFuncSetAttribute(fused_k, cudaFuncAttributeMaxDynamicSharedMemorySize, SMEMSZ);

    mask_k<<<131072, 256>>>(CFG1, LFG1, CFG2, LFG2, g1rk, g2rk, mlp1, mlp2);
    litgemm_k<<<dim3(BN / 128, 1, 2), 256>>>(LIT1, Wl1, LIT2, Wl2,
                                             cw1, cb1, cw2, cb2, lw1, lb1, lw2, lb2);
    sgemm_xz<<<dim3(BB * TT / 128, 3, 2), 256>>>(SEM1, g1k, g1b, SEM2, g2k, g2b);
    gru_k<<<64, 768>>>(g1b, g2b);   // ncu capture slot (my #4)

    for (int it = 0; it < NITER; it++) {
        fused_k<<<dim3(4, 1, 128), 256, SMEMSZ>>>(
            cw1, cb1, cw2, cb2, lw1, lb1, lw2, lb2,
            (it == NITER - 1) ? 1 : 0, it & 1, (it + 1) & 1);
    }

    outfinal_k<<<BB, 128>>>(Wout, bout, (float*)d_out);
}

// round 13
// speedup vs baseline: 1.0431x; 1.0431x over previous
#include <cuda_runtime.h>
#include <cuda_fp16.h>
#include <math.h>

#define BB 32
#define NN 512
#define TT 64
#define EE 128
#define OO 64
#define NITER 5
#define BNE (BB*NN*EE)      // 2^21
#define BN  (BB*NN)
#define L2E 1.442695040888963f

// ---------------- scratch ----------------
__device__ float    g_lit[2][BNE];
__device__ float    g_ah1[2][4][BN];
__device__ float    g_ah2[2][4][BN];
__device__ unsigned g_mask[4][BN*16];
__device__ float    g_xz[2][BB*TT*3*EE];
__device__ float    g_hfin[2][BB*EE];
__device__ float    g_rkT[2][3*EE*EE];
__device__ float    g_mid[2][BB*3*EE];
__device__ __half   g_embh[2][4ll*BNE];
__device__ __half   g_w1h[EE*EE];
__device__ __half   g_w2h[EE*EE];

// ================= helpers =================
__device__ __forceinline__ unsigned sptr(const void* p) {
    return (unsigned)__cvta_generic_to_shared(p);
}
__device__ __forceinline__ void cpasync16(unsigned s, const void* g) {
    asm volatile("cp.async.cg.shared.global [%0], [%1], 16;\n" :: "r"(s), "l"(g));
}
__device__ __forceinline__ void ldsm4(unsigned* r, unsigned addr) {
    asm volatile("ldmatrix.sync.aligned.m8n8.x4.shared.b16 {%0,%1,%2,%3},[%4];\n"
                 : "=r"(r[0]), "=r"(r[1]), "=r"(r[2]), "=r"(r[3]) : "r"(addr));
}
__device__ __forceinline__ void ldsm4t(unsigned* r, unsigned addr) {
    asm volatile("ldmatrix.sync.aligned.m8n8.x4.trans.shared.b16 {%0,%1,%2,%3},[%4];\n"
                 : "=r"(r[0]), "=r"(r[1]), "=r"(r[2]), "=r"(r[3]) : "r"(addr));
}
__device__ __forceinline__ void mma16816(float* d, const unsigned* a, unsigned b0, unsigned b1) {
    asm volatile(
        "mma.sync.aligned.m16n8k16.row.col.f32.f16.f16.f32 "
        "{%0,%1,%2,%3},{%4,%5,%6,%7},{%8,%9},{%0,%1,%2,%3};\n"
        : "+f"(d[0]), "+f"(d[1]), "+f"(d[2]), "+f"(d[3])
        : "r"(a[0]), "r"(a[1]), "r"(a[2]), "r"(a[3]), "r"(b0), "r"(b1));
}
__device__ __forceinline__ float ex2a(float x) {
    float y; asm("ex2.approx.f32 %0,%1;\n" : "=f"(y) : "f"(x)); return y;
}
__device__ __forceinline__ float tanha(float x) {
    float y; asm("tanh.approx.f32 %0,%1;\n" : "=f"(y) : "f"(x)); return y;
}

__device__ __forceinline__ void mma_ks(const __half* as_, int astr, int aoff,
                                       const __half* bs_, int ks,
                                       int wm, int wn, int lane, float acc[4][4][4])
{
    unsigned a[4][4], bfr[2][4];
#pragma unroll
    for (int mi = 0; mi < 4; mi++)
        ldsm4(a[mi], sptr(as_ + (wm + mi * 16 + (lane & 15)) * astr + aoff + (lane >> 4) * 8));
#pragma unroll
    for (int nb = 0; nb < 2; nb++)
        ldsm4t(bfr[nb], sptr(bs_ + (ks * 16 + (lane & 15)) * 136 + wn + nb * 16 + (lane >> 4) * 8));
#pragma unroll
    for (int mi = 0; mi < 4; mi++)
#pragma unroll
        for (int j = 0; j < 4; j++)
            mma16816(acc[mi][j], a[mi], bfr[j >> 1][(j & 1) * 2], bfr[j >> 1][(j & 1) * 2 + 1]);
}

// ================= fused per-iteration kernel =================
#define OFF_XL   9728
#define OFF_AS   (OFF_XL + 34816)     // 44544
#define OFF_BS   (OFF_AS + 30720)     // 75264
#define SMEMSZ   (OFF_BS + 26112)     // 101376

__global__ void __launch_bounds__(256, 2) fused_k(
    const float* __restrict__ cw1, const float* __restrict__ cb1,
    const float* __restrict__ cw2, const float* __restrict__ cb2,
    const float* __restrict__ lw1, const float* __restrict__ lb1,
    const float* __restrict__ lw2, const float* __restrict__ lb2,
    int last, int rd, int wr)
{
    extern __shared__ __align__(16) char dyn[];
    float* s_ah1 = (float*)dyn;
    float* s_iZ  = s_ah1 + 128;
    float* s_ah2 = s_iZ + 128;
    float* s_red = s_ah2 + 512;
    float* s_sd1 = s_red + 256;
    float* s_sd2 = s_sd1 + 128;
    float* s_col = s_sd2 + 128;
    float* s_w1v = s_col + 128;
    float* s_w2v = s_w1v + 128;
    float* s_E   = s_w2v + 128;
    __half2* s_Fh = (__half2*)(s_E + 256);
    __half* XL = (__half*)(dyn + OFF_XL);
    unsigned* s_mask = (unsigned*)XL;
    __half* Asp = (__half*)(dyn + OFF_AS);
    __half* Bsp = (__half*)(dyn + OFF_BS);
    __half* Ws  = (__half*)(dyn + OFF_AS);

    const int z = blockIdx.z;
    const int c = z >> 5, b = z & 31;
    const int rowBase = blockIdx.x * 128;
    const int rowOff = b * NN + rowBase;
    const int tid = threadIdx.x, warp = tid >> 5, lane = tid & 31;
    const int wm = (warp >> 2) * 64, wn = (warp & 3) * 32;

    // ---------- prologue ----------
    const float* w1src = (c & 1) ? lw1 : cw1;
    const float* w2src = (c & 1) ? lw2 : cw2;
    const float bb1 = ((c & 1) ? lb1 : cb1)[0];
    const float bb2 = ((c & 1) ? lb2 : cb2)[0];
    if (tid < 128) {
        s_ah1[tid] = g_ah1[rd][c][rowOff + tid];
        s_w1v[tid] = w1src[tid];
        s_w2v[tid] = w2src[tid];
        ((float4*)s_ah2)[tid] = ((const float4*)(g_ah2[rd][c] + b * NN))[tid];
    }
    {
        const uint4* msrc = (const uint4*)(g_mask[c] + (long long)rowOff * 16);
        uint4* mdst = (uint4*)s_mask;
        mdst[tid] = msrc[tid];
        mdst[tid + 256] = msrc[tid + 256];
    }
    __syncthreads();

    // separable-exp precompute
#pragma unroll
    for (int i = tid; i < 512; i += 256) {
        float bq = fminf(s_ah2[i], 10.f);
        s_Fh[i] = __floats2half2_rn(ex2a(bq * L2E), ex2a(0.2f * bq * L2E));
    }
    if (tid < 128) {
        float a = s_ah1[tid];
        float K = a > 0.f ? a : 0.2f * a;
        ((float2*)s_E)[tid] = make_float2(ex2a((a - K) * L2E), ex2a((0.2f * a - K) * L2E));
    }
    __syncthreads();

    const int br = tid >> 4, bs4 = tid & 15;
    auto loadB2 = [&](const __half* src, int krow0, int stg) {
#pragma unroll
        for (int i = 0; i < 2; i++) {
            int r = br + i * 16;
            cpasync16(sptr(Bsp + stg * 4352 + r * 136 + bs4 * 8),
                      src + (long long)(krow0 + r) * 128 + bs4 * 8);
        }
        asm volatile("cp.async.commit_group;\n");
    };
    auto loadW = [&](const __half* src) {
#pragma unroll
        for (int i = 0; i < 8; i++) {
            int seg = i * 256 + tid;
            int r = seg >> 4, s16 = seg & 15;
            cpasync16(sptr(Ws + r * 136 + s16 * 8), src + r * 128 + s16 * 8);
        }
        asm volatile("cp.async.commit_group;\ncp.async.wait_group 0;\n" ::: "memory");
    };

    const int gr = tid >> 1, j0 = (tid & 1) * 16;
    const float negA = -s_ah1[gr];
    const float2 Ee = ((const float2*)s_E)[gr];
    float psum = 0.f;
    auto genP = [&](int ch, int stg) {
        unsigned mw = s_mask[gr * 16 + ch] >> j0;
        const float4* a2 = (const float4*)(s_ah2 + ch * 32 + j0);
        const uint4* f4 = (const uint4*)(s_Fh + ch * 32 + j0);
        __half2 hv[8];
#pragma unroll
        for (int q = 0; q < 4; q++) {
            float4 v = a2[q];
            uint4 fq = f4[q];
            const __half2* fh = (const __half2*)&fq;
            float vv[4] = {v.x, v.y, v.z, v.w};
            float p[4];
#pragma unroll
            for (int t = 0; t < 4; t++) {
                bool pos = vv[t] > negA;
                float2 ff = __half22float2(fh[t]);
                float pv = (pos ? Ee.x : Ee.y) * (pos ? ff.x : ff.y);
                p[t] = ((mw >> (q * 4 + t)) & 1u) ? pv : 0.f;
                psum += p[t];
            }
            hv[q * 2 + 0] = __floats2half2_rn(p[0], p[1]);
            hv[q * 2 + 1] = __floats2half2_rn(p[2], p[3]);
        }
        __half* as = Asp + stg * 5120;
        *(uint4*)(as + gr * 40 + j0) = *(uint4*)&hv[0];
        *(uint4*)(as + gr * 40 + j0 + 8) = *(uint4*)&hv[4];
    };

    float acc[4][4][4];
#pragma unroll
    for (int mi = 0; mi < 4; mi++)
#pragma unroll
        for (int j = 0; j < 4; j++)
#pragma unroll
            for (int q = 0; q < 4; q++) acc[mi][j][q] = 0.f;

    // ---------- phase 1: O = P @ emb ----------
    const __half* Bp = g_embh[rd] + (long long)z * (NN * EE);
    loadB2(Bp, 0, 0);
    loadB2(Bp, 32, 1);
    genP(0, 0);
    genP(1, 1);
    asm volatile("cp.async.wait_group 1;\n");
    __syncthreads();
#pragma unroll 4
    for (int ch = 0; ch < 16; ch++) {
        if (ch + 2 < 16) {
            loadB2(Bp, (ch + 2) * 32, (ch + 2) % 3);
            genP(ch + 2, (ch + 2) % 3);
        }
        const __half* as = Asp + (ch % 3) * 5120;
        const __half* bs_ = Bsp + (ch % 3) * 4352;
#pragma unroll
        for (int ks = 0; ks < 2; ks++)
            mma_ks(as, 40, ks * 16, bs_, ks, wm, wn, lane, acc);
        if (ch + 2 < 16) asm volatile("cp.async.wait_group 1;\n");
        else             asm volatile("cp.async.wait_group 0;\n");
        __syncthreads();
    }

    s_red[tid] = psum;
    __syncthreads();
    if (tid < 128) {
        float s2 = s_red[2 * tid] + s_red[2 * tid + 1];
        s_iZ[tid] = (s2 > 0.f) ? __fdividef(1.f, s2) : 0.f;
    }
    __syncthreads();

#pragma unroll
    for (int mi = 0; mi < 4; mi++)
#pragma unroll
        for (int h = 0; h < 2; h++) {
            const int r = wm + mi * 16 + (lane >> 2) + h * 8;
            const float rs = s_iZ[r];
#pragma unroll
            for (int j = 0; j < 4; j++) {
                const int c0 = wn + j * 8 + (lane & 3) * 2;
                *(__half2*)(XL + r * 136 + c0) =
                    __floats2half2_rn(acc[mi][j][h * 2] * rs, acc[mi][j][h * 2 + 1] * rs);
            }
        }
    __syncthreads();

    // ---------- phase 2: H = relu(O @ W1), whole W1 staged ----------
#pragma unroll
    for (int mi = 0; mi < 4; mi++)
#pragma unroll
        for (int j = 0; j < 4; j++)
#pragma unroll
            for (int q = 0; q < 4; q++) acc[mi][j][q] = 0.f;
    loadW(g_w1h);
    __syncthreads();
#pragma unroll
    for (int st = 0; st < 8; st++)
        mma_ks(XL, 136, st * 16, Ws, st, wm, wn, lane, acc);
    __syncthreads();
#pragma unroll
    for (int mi = 0; mi < 4; mi++)
#pragma unroll
        for (int h = 0; h < 2; h++) {
            const int r = wm + mi * 16 + (lane >> 2) + h * 8;
#pragma unroll
            for (int j = 0; j < 4; j++) {
                const int c0 = wn + j * 8 + (lane & 3) * 2;
                *(__half2*)(XL + r * 136 + c0) =
                    __floats2half2_rn(fmaxf(acc[mi][j][h * 2], 0.f),
                                      fmaxf(acc[mi][j][h * 2 + 1], 0.f));
            }
        }
    if (tid < 128) { s_sd1[tid] = 0.f; s_sd2[tid] = 0.f; s_col[tid] = 0.f; }

    // ---------- phase 3: E = tanh(lit + H @ W2), whole W2 staged ----------
#pragma unroll
    for (int mi = 0; mi < 4; mi++)
#pragma unroll
        for (int j = 0; j < 4; j++)
#pragma unroll
            for (int q = 0; q < 4; q++) acc[mi][j][q] = 0.f;
    loadW(g_w2h);
    __syncthreads();
#pragma unroll
    for (int st = 0; st < 8; st++)
        mma_ks(XL, 136, st * 16, Ws, st, wm, wn, lane, acc);

    // epilogue
    const float* litp = g_lit[c >> 1] + ((long long)(b * NN + rowBase)) * EE;
    __half* embp = g_embh[wr] + (long long)z * (NN * EE) + (long long)rowBase * EE;
    float colacc[8];
#pragma unroll
    for (int q = 0; q < 8; q++) colacc[q] = 0.f;
#pragma unroll
    for (int mi = 0; mi < 4; mi++)
#pragma unroll
        for (int h = 0; h < 2; h++) {
            const int r = wm + mi * 16 + (lane >> 2) + h * 8;
            float d1 = 0.f, d2 = 0.f;
#pragma unroll
            for (int j = 0; j < 4; j++) {
                const int c0 = wn + j * 8 + (lane & 3) * 2;
                float2 l = *(const float2*)(litp + (long long)r * EE + c0);
                float x0 = tanha(l.x + acc[mi][j][h * 2]);
                float x1 = tanha(l.y + acc[mi][j][h * 2 + 1]);
                *(__half2*)(embp + (long long)r * EE + c0) = __floats2half2_rn(x0, x1);
                d1 = fmaf(x0, s_w1v[c0], fmaf(x1, s_w1v[c0 + 1], d1));
                d2 = fmaf(x0, s_w2v[c0], fmaf(x1, s_w2v[c0 + 1], d2));
                colacc[j * 2 + 0] += x0;
                colacc[j * 2 + 1] += x1;
            }
            atomicAdd(&s_sd1[r], d1);
            atomicAdd(&s_sd2[r], d2);
        }
    if (last) {
#pragma unroll
        for (int j = 0; j < 4; j++) {
            const int c0 = wn + j * 8 + (lane & 3) * 2;
            atomicAdd(&s_col[c0], colacc[j * 2]);
            atomicAdd(&s_col[c0 + 1], colacc[j * 2 + 1]);
        }
    }
    __syncthreads();
    if (tid < 128) {
        g_ah1[wr][c][rowOff + tid] = s_sd1[tid] + bb1;
        g_ah2[wr][c][rowOff + tid] = s_sd2[tid] + bb2;
        if (last)
            atomicAdd(&g_mid[c >> 1][b * 3 * EE + (c & 1) * EE + tid], s_col[tid]);
    }
}

// ---------------- literal GEMM + fused init epilogue ----------------
__global__ void __launch_bounds__(256) litgemm_k(
    const float* __restrict__ L1, const float* __restrict__ W1,
    const float* __restrict__ L2, const float* __restrict__ W2,
    const float* __restrict__ cw1, const float* __restrict__ cb1,
    const float* __restrict__ cw2, const float* __restrict__ cb2,
    const float* __restrict__ lw1, const float* __restrict__ lb1,
    const float* __restrict__ lw2, const float* __restrict__ lb2)
{
    constexpr int BM = 128, BK = 8, TM = 8, TN = 8;
    __shared__ float As[BK][BM];
    __shared__ float Bsf[BK][128];
    __shared__ float s_w[4][128];
    const int s = blockIdx.z;
    const float* A = s ? L2 : L1;
    const float* Bm = s ? W2 : W1;
    float* C = g_lit[s];
    const int rowBase = blockIdx.x * BM;
    const int tid = threadIdx.x;
    const int tx = tid & 15, ty = tid >> 4;
    const int aRow = tid >> 1, aCol = (tid & 1) * 4;
    const int bRow = tid >> 5, bCol = (tid & 31) * 4;
    for (int i = tid; i < 512; i += 256) {
        int type = i >> 7, k = i & 127;
        const float* src = (type == 0) ? cw1 : (type == 1) ? cw2 : (type == 2) ? lw1 : lw2;
        s_w[type][k] = src[k];
    }
    float acc[TM][TN];
#pragma unroll
    for (int i = 0; i < TM; i++)
#pragma unroll
        for (int j = 0; j < TN; j++) acc[i][j] = 0.f;
    const float* Aptr = A + (long long)(rowBase + aRow) * EE + aCol;
    const float* Bptr = Bm + (long long)bRow * EE + bCol;
    for (int k0 = 0; k0 < EE; k0 += BK) {
        float4 av = *(const float4*)(Aptr + k0);
        float4 bv = *(const float4*)(Bptr + (long long)k0 * EE);
        As[aCol + 0][aRow] = av.x; As[aCol + 1][aRow] = av.y;
        As[aCol + 2][aRow] = av.z; As[aCol + 3][aRow] = av.w;
        *(float4*)&Bsf[bRow][bCol] = bv;
        __syncthreads();
#pragma unroll
        for (int k = 0; k < BK; k++) {
            float ra[TM], rb[TN];
            *(float4*)&ra[0] = *(const float4*)&As[k][ty * TM];
            *(float4*)&ra[4] = *(const float4*)&As[k][ty * TM + 4];
            *(float4*)&rb[0] = *(const float4*)&Bsf[k][tx * TN];
            *(float4*)&rb[4] = *(const float4*)&Bsf[k][tx * TN + 4];
#pragma unroll
            for (int i = 0; i < TM; i++)
#pragma unroll
                for (int j = 0; j < TN; j++)
                    acc[i][j] = fmaf(ra[i], rb[j], acc[i][j]);
        }
        __syncthreads();
    }
    const float bc1 = cb1[0], bc2 = cb2[0], bl1 = lb1[0], bl2 = lb2[0];
#pragma unroll
    for (int i = 0; i < TM; i++) {
        const int row = rowBase + ty * TM + i;
        const int bb = row >> 9, n = row & 511;
        float* crow = C + (long long)row * EE + tx * TN;
        __half* e0 = g_embh[0] + ((long long)(s * 64 + bb) * NN + n) * EE + tx * TN;
        __half* e1 = g_embh[0] + ((long long)(s * 64 + 32 + bb) * NN + n) * EE + tx * TN;
        float dc1 = 0.f, dc2 = 0.f, dl1 = 0.f, dl2 = 0.f;
#pragma unroll
        for (int j0 = 0; j0 < TN; j0 += 4) {
            float4 v;
            v.x = acc[i][j0 + 0]; v.y = acc[i][j0 + 1];
            v.z = acc[i][j0 + 2]; v.w = acc[i][j0 + 3];
            *(float4*)(crow + j0) = v;
            float rv[4] = {fmaxf(v.x, 0.f), fmaxf(v.y, 0.f), fmaxf(v.z, 0.f), fmaxf(v.w, 0.f)};
            __half2 h01 = __floats2half2_rn(rv[0], rv[1]);
            __half2 h23 = __floats2half2_rn(rv[2], rv[3]);
            *(__half2*)(e0 + j0) = h01; *(__half2*)(e0 + j0 + 2) = h23;
            *(__half2*)(e1 + j0) = h01; *(__half2*)(e1 + j0 + 2) = h23;
#pragma unroll
            for (int q = 0; q < 4; q++) {
                const int col = tx * TN + j0 + q;
                dc1 = fmaf(rv[q], s_w[0][col], dc1);
                dc2 = fmaf(rv[q], s_w[1][col], dc2);
                dl1 = fmaf(rv[q], s_w[2][col], dl1);
                dl2 = fmaf(rv[q], s_w[3][col], dl2);
            }
        }
#pragma unroll
        for (int o = 8; o; o >>= 1) {
            dc1 += __shfl_xor_sync(0xffffffffu, dc1, o);
            dc2 += __shfl_xor_sync(0xffffffffu, dc2, o);
            dl1 += __shfl_xor_sync(0xffffffffu, dl1, o);
            dl2 += __shfl_xor_sync(0xffffffffu, dl2, o);
        }
        if (tx == 0) {
            g_ah1[0][2 * s][row] = dc1 + bc1;
            g_ah2[0][2 * s][row] = dc2 + bc2;
            g_ah1[0][2 * s + 1][row] = dl1 + bl1;
            g_ah2[0][2 * s + 1][row] = dl2 + bl2;
        }
    }
}

// ---------------- xz GEMM, z-batched over both sides ----------------
__global__ void __launch_bounds__(256) sgemm_xz(
    const float* __restrict__ A1, const float* __restrict__ B1, const float* __restrict__ e1,
    const float* __restrict__ A2, const float* __restrict__ B2, const float* __restrict__ e2)
{
    constexpr int BM = 128, BNt = 128, BK = 8, TM = 8, TN = 8;
    constexpr int Nn = 3 * EE, K = EE;
    __shared__ float As[BK][BM];
    __shared__ float Bsf[BK][BNt];
    const int side = blockIdx.z;
    const float* A = side ? A2 : A1;
    const float* Bm = side ? B2 : B1;
    const float* extra = side ? e2 : e1;
    float* C = g_xz[side];
    const int rowBase = blockIdx.x * BM;
    const int colBase = blockIdx.y * BNt;
    const int tid = threadIdx.x;
    const int tx = tid & 15, ty = tid >> 4;
    const int aRow = tid >> 1, aCol = (tid & 1) * 4;
    const int bRow = tid >> 5, bCol = (tid & 31) * 4;
    float acc[TM][TN];
#pragma unroll
    for (int i = 0; i < TM; i++)
#pragma unroll
        for (int j = 0; j < TN; j++) acc[i][j] = 0.f;
    const float* Aptr = A + (long long)(rowBase + aRow) * K + aCol;
    const float* Bptr = Bm + (long long)bRow * Nn + colBase + bCol;
    for (int k0 = 0; k0 < K; k0 += BK) {
        float4 av = *(const float4*)(Aptr + k0);
        float4 bv = *(const float4*)(Bptr + (long long)k0 * Nn);
        As[aCol + 0][aRow] = av.x; As[aCol + 1][aRow] = av.y;
        As[aCol + 2][aRow] = av.z; As[aCol + 3][aRow] = av.w;
        *(float4*)&Bsf[bRow][bCol] = bv;
        __syncthreads();
#pragma unroll
        for (int k = 0; k < BK; k++) {
            float ra[TM], rb[TN];
            *(float4*)&ra[0] = *(const float4*)&As[k][ty * TM];
            *(float4*)&ra[4] = *(const float4*)&As[k][ty * TM + 4];
            *(float4*)&rb[0] = *(const float4*)&Bsf[k][tx * TN];
            *(float4*)&rb[4] = *(const float4*)&Bsf[k][tx * TN + 4];
#pragma unroll
            for (int i = 0; i < TM; i++)
#pragma unroll
                for (int j = 0; j < TN; j++)
                    acc[i][j] = fmaf(ra[i], rb[j], acc[i][j]);
        }
        __syncthreads();
    }
#pragma unroll
    for (int i = 0; i < TM; i++) {
        int row = rowBase + ty * TM + i;
        float* crow = C + (long long)row * Nn + colBase + tx * TN;
#pragma unroll
        for (int j0 = 0; j0 < TN; j0 += 4) {
            float4 v;
            v.x = acc[i][j0 + 0] + extra[colBase + tx * TN + j0 + 0];
            v.y = acc[i][j0 + 1] + extra[colBase + tx * TN + j0 + 1];
            v.z = acc[i][j0 + 2] + extra[colBase + tx * TN + j0 + 2];
            v.w = acc[i][j0 + 3] + extra[colBase + tx * TN + j0 + 3];
            *(float4*)(crow + j0) = v;
        }
    }
}

// ---------------- G -> bitmask + transpose rk + zero g_mid + fp16 weights ----------------
__global__ void __launch_bounds__(256) mask_k(
    const int* __restrict__ g0, const int* __restrict__ g1,
    const int* __restrict__ g2, const int* __restrict__ g3,
    const float* __restrict__ rk1, const float* __restrict__ rk2,
    const float* __restrict__ m1, const float* __restrict__ m2)
{
    const long long flat = (long long)blockIdx.x * 256 + threadIdx.x;
    if (flat < 2 * BB * 3 * EE) ((float*)g_mid)[flat] = 0.f;
    if (flat < 2 * 3 * EE * EE) {
        const int s = (int)(flat / (3 * EE * EE));
        const int r = (int)(flat % (3 * EE * EE));
        const int j = r / EE, k = r % EE;
        const float* rk = s ? rk2 : rk1;
        g_rkT[s][r] = rk[k * 3 * EE + j];
    }
    if (flat < EE * EE) g_w1h[flat] = __float2half_rn(m1[flat]);
    else if (flat < 2 * EE * EE) g_w2h[flat - EE * EE] = __float2half_rn(m2[flat - EE * EE]);
    const long long gid = flat >> 5;
    const int lane = threadIdx.x & 31;
    const int c = (int)(gid >> 18);
    const long long r = gid & 262143;
    const long long rowrem = r >> 4;
    const int w = (int)(r & 15);
    const int* G = (c == 0) ? g0 : (c == 1) ? g1 : (c == 2) ? g2 : g3;
    int val = G[rowrem * NN + w * 32 + lane];
    unsigned m = __ballot_sync(0xffffffffu, val != 0);
    if (lane == 0) g_mask[c][rowrem * 16 + w] = m;
}

// ---------------- GRU (reset_after): register weights, 384 thr (R11-proven) ----------------
__global__ void __launch_bounds__(384, 1) gru_k(const float* __restrict__ b1,
                                                const float* __restrict__ b2)
{
    const int s = blockIdx.x >> 5, b = blockIdx.x & 31;
    const float* xz = g_xz[s] + (long long)b * TT * 3 * EE;
    const float* br = (s ? b2 : b1) + 3 * EE;
    const int j = threadIdx.x;

    float4 w[32];
    {
        const float4* wsrc = (const float4*)(g_rkT[s] + (long long)j * EE);
#pragma unroll
        for (int i = 0; i < 32; i++) w[i] = wsrc[i];
    }

    __shared__ __align__(16) float hs[EE];
    __shared__ float hzs[3 * EE];
    __shared__ float xs[3 * EE];
    if (j < EE) hs[j] = 0.f;
    const float brj = br[j];
    __syncthreads();

    for (int t = 0; t < TT; t++) {
        const float xv = xz[t * 3 * EE + j];
        const float4* h4 = (const float4*)hs;
        float a[8];
#pragma unroll
        for (int u = 0; u < 8; u++) a[u] = 0.f;
#pragma unroll
        for (int qq = 0; qq < 32; qq += 8) {
#pragma unroll
            for (int u = 0; u < 8; u++) {
                float4 wv = w[qq + u], hv = h4[qq + u];
                a[u] = fmaf(wv.x, hv.x, a[u]); a[u] = fmaf(wv.y, hv.y, a[u]);
                a[u] = fmaf(wv.z, hv.z, a[u]); a[u] = fmaf(wv.w, hv.w, a[u]);
            }
        }
        hzs[j] = ((a[0] + a[1]) + (a[2] + a[3])) + ((a[4] + a[5]) + (a[6] + a[7])) + brj;
        xs[j] = xv;
        __syncthreads();
        if (j < EE) {
            float zz = __fdividef(1.f, 1.f + __expf(-(xs[j] + hzs[j])));
            float rr = __fdividef(1.f, 1.f + __expf(-(xs[EE + j] + hzs[EE + j])));
            float hh = tanha(xs[2 * EE + j] + rr * hzs[2 * EE + j]);
            hs[j] = zz * hs[j] + (1.f - zz) * hh;
        }
        __syncthreads();
    }
    if (j < EE) g_hfin[s][b * EE + j] = hs[j];
}

// ---------------- merged head ----------------
__global__ void __launch_bounds__(128) outfinal_k(const float* __restrict__ Wout,
                                                  const float* __restrict__ bout,
                                                  float* __restrict__ out)
{
    const int b = blockIdx.x, tid = threadIdx.x;
    __shared__ float ms[2][3 * EE];
    __shared__ float sh[128];
    __shared__ float red[6];
    for (int i = tid; i < 2 * 3 * EE; i += 128) {
        int s = i / (3 * EE), k = i % (3 * EE);
        ms[s][k] = (k < 2 * EE) ? g_mid[s][b * 3 * EE + k] : g_hfin[s][b * EE + (k - 2 * EE)];
    }
    __syncthreads();
    const int s = tid >> 6, o = tid & 63;
    float acc = bout[o];
    for (int k = 0; k < 3 * EE; k++) acc = fmaf(ms[s][k], Wout[k * OO + o], acc);
    sh[tid] = acc;
    __syncthreads();
    if (tid < 64) {
        float x = sh[tid], y = sh[tid + 64];
        float d = x * y, nx = x * x, ny = y * y;
#pragma unroll
        for (int off = 16; off; off >>= 1) {
            d  += __shfl_xor_sync(0xffffffffu, d, off);
            nx += __shfl_xor_sync(0xffffffffu, nx, off);
            ny += __shfl_xor_sync(0xffffffffu, ny, off);
        }
        if ((tid & 31) == 0) {
            red[(tid >> 5) * 3 + 0] = d;
            red[(tid >> 5) * 3 + 1] = nx;
            red[(tid >> 5) * 3 + 2] = ny;
        }
    }
    __syncthreads();
    if (tid == 0) {
        float D = red[0] + red[3], X = red[1] + red[4], Y = red[2] + red[5];
        float cosv = D * rsqrtf(fmaxf(X, 1e-12f)) * rsqrtf(fmaxf(Y, 1e-12f));
        out[b] = (cosv + 1.f) * 0.5f;
    }
}

// ---------------- launch ----------------
extern "C" void kernel_launch(void* const* d_in, const int* in_sizes, int n_in,
                              void* d_out, int out_size)
{
    const int*   CFG1 = (const int*)d_in[0];
    const int*   LFG1 = (const int*)d_in[1];
    const float* LIT1 = (const float*)d_in[2];
    const float* SEM1 = (const float*)d_in[3];
    const int*   CFG2 = (const int*)d_in[4];
    const int*   LFG2 = (const int*)d_in[5];
    const float* LIT2 = (const float*)d_in[6];
    const float* SEM2 = (const float*)d_in[7];
    const float* Wl1  = (const float*)d_in[8];
    const float* g1k  = (const float*)d_in[9];
    const float* g1rk = (const float*)d_in[10];
    const float* g1b  = (const float*)d_in[11];
    const float* Wl2  = (const float*)d_in[12];
    const float* g2k  = (const float*)d_in[13];
    const float* g2rk = (const float*)d_in[14];
    const float* g2b  = (const float*)d_in[15];
    const float* cw1  = (const float*)d_in[16];
    const float* cb1  = (const float*)d_in[17];
    const float* cw2  = (const float*)d_in[18];
    const float* cb2  = (const float*)d_in[19];
    const float* lw1  = (const float*)d_in[20];
    const float* lb1  = (const float*)d_in[21];
    const float* lw2  = (const float*)d_in[22];
    const float* lb2  = (const float*)d_in[23];
    const float* mlp1 = (const float*)d_in[24];
    const float* mlp2 = (const float*)d_in[25];
    const float* Wout = (const float*)d_in[26];
    const float* bout = (const float*)d_in[27];

    cudaFuncSetAttribute(fused_k, cudaFuncAttributeMaxDynamicSharedMemorySize, SMEMSZ);

    mask_k<<<131072, 256>>>(CFG1, LFG1, CFG2, LFG2, g1rk, g2rk, mlp1, mlp2);
    litgemm_k<<<dim3(BN / 128, 1, 2), 256>>>(LIT1, Wl1, LIT2, Wl2,
                                             cw1, cb1, cw2, cb2, lw1, lb1, lw2, lb2);
    sgemm_xz<<<dim3(BB * TT / 128, 3, 2), 256>>>(SEM1, g1k, g1b, SEM2, g2k, g2b);
    gru_k<<<64, 384>>>(g1b, g2b);   // ncu capture slot (my #4)

    for (int it = 0; it < NITER; it++) {
        fused_k<<<dim3(4, 1, 128), 256, SMEMSZ>>>(
            cw1, cb1, cw2, cb2, lw1, lb1, lw2, lb2,
            (it == NITER - 1) ? 1 : 0, it & 1, (it + 1) & 1);
    }

    outfinal_k<<<BB, 128>>>(Wout, bout, (float*)d_out);
}